// round 6
// baseline (speedup 1.0000x reference)
#include <cuda_runtime.h>
#include <math.h>

// Problem constants (fixed shapes)
#define B      2
#define HEADS  8
#define CQ     48
#define CK     12
#define CTOT   384      // HEADS*CQ
#define P      96       // pooled channels = HEADS*CK
#define L      4096
#define TREP   16
#define HW     65536    // 256*256 = TREP*L
#define NROWS  (B*CTOT)     // 768 q rows
#define KROWS  (B*P)        // 192 k rows

typedef unsigned long long ull;

// Scratch (static device globals — no allocation)
__device__ float g_kn[KROWS * L];      // pooled + L2-normalized kv   (3.1 MB)
__device__ float g_attn[NROWS * CK];   // softmax(attn)
__device__ float g_M[B * CTOT * P];    // W folded with attn
__device__ float g_f[NROWS * L];       // pre-replication output      (12.6 MB)

__device__ __forceinline__ float warpSum(float v) {
#pragma unroll
    for (int o = 16; o > 0; o >>= 1) v += __shfl_xor_sync(0xffffffffu, v, o);
    return v;
}

#if defined(__CUDA_ARCH__) && (__CUDA_ARCH__ >= 1000)
__device__ __forceinline__ ull pack2(float x) {      // (x, x) as f32x2
    ull r;
    asm("mov.b64 %0, {%1, %1};" : "=l"(r) : "f"(x));
    return r;
}
__device__ __forceinline__ void ffma2(ull& d, ull a, ull b) {  // d += a*b (2x fp32)
    asm("fma.rn.f32x2 %0, %1, %2, %0;" : "+l"(d) : "l"(a), "l"(b));
}
#else
__device__ __forceinline__ ull pack2(float x) {
    union { float f[2]; ull u; } t; t.f[0] = x; t.f[1] = x; return t.u;
}
__device__ __forceinline__ void ffma2(ull& d, ull a, ull b) {
    union { float f[2]; ull u; } da, aa, ba;
    da.u = d; aa.u = a; ba.u = b;
    da.f[0] = fmaf(aa.f[0], ba.f[0], da.f[0]);
    da.f[1] = fmaf(aa.f[1], ba.f[1], da.f[1]);
    d = da.u;
}
#endif

// ---------------------------------------------------------------------------
// K2: avg_pool1d over channel groups of 4 + L2 normalize each pooled row.
// ---------------------------------------------------------------------------
__global__ void __launch_bounds__(1024) k_pool_kv(const float* __restrict__ kv) {
    int row = blockIdx.x;               // b*P + i
    int b = row / P, i = row % P;
    int tid = threadIdx.x;
    const float4* base = reinterpret_cast<const float4*>(kv + ((size_t)b * CTOT + 4 * i) * L);
    float4 v0 = base[tid];
    float4 v1 = base[1024 + tid];
    float4 v2 = base[2048 + tid];
    float4 v3 = base[3072 + tid];
    float4 p;
    p.x = 0.25f * (v0.x + v1.x + v2.x + v3.x);
    p.y = 0.25f * (v0.y + v1.y + v2.y + v3.y);
    p.z = 0.25f * (v0.z + v1.z + v2.z + v3.z);
    p.w = 0.25f * (v0.w + v1.w + v2.w + v3.w);
    float ss = p.x * p.x + p.y * p.y + p.z * p.z + p.w * p.w;

    ss = warpSum(ss);
    __shared__ float sred[32];
    __shared__ float s_scale;
    int lane = tid & 31, w = tid >> 5;
    if (lane == 0) sred[w] = ss;
    __syncthreads();
    if (w == 0) {
        float v = sred[lane];
        v = warpSum(v);
        if (lane == 0) s_scale = 1.f / fmaxf(sqrtf(v), 1e-12f);
    }
    __syncthreads();
    float sc = s_scale;
    p.x *= sc; p.y *= sc; p.z *= sc; p.w *= sc;
    reinterpret_cast<float4*>(g_kn + (size_t)row * L)[tid] = p;
}

// ---------------------------------------------------------------------------
// K1: fold Q over 16 tiles + dot vs 12 kn rows + softmax -> attn row.
// One block (256 threads) per q-row; 768 blocks.
// ---------------------------------------------------------------------------
__global__ void __launch_bounds__(256) k_fold_attn(const float* __restrict__ Q) {
    int row = blockIdx.x;
    int b = row / CTOT;
    int c = row % CTOT;
    int h = c / CQ;
    int tid = threadIdx.x;
    int lane = tid & 31, w = tid >> 5;

    const float4* qp = reinterpret_cast<const float4*>(Q + (size_t)row * HW);
    float4 acc[4];
#pragma unroll
    for (int cc = 0; cc < 4; cc++) acc[cc] = make_float4(0.f, 0.f, 0.f, 0.f);
    float ss = 0.f;

#pragma unroll
    for (int t = 0; t < TREP; t++) {
        float4 v[4];
#pragma unroll
        for (int cc = 0; cc < 4; cc++) v[cc] = qp[t * 1024 + cc * 256 + tid];
#pragma unroll
        for (int cc = 0; cc < 4; cc++) {
            acc[cc].x += v[cc].x; acc[cc].y += v[cc].y;
            acc[cc].z += v[cc].z; acc[cc].w += v[cc].w;
            ss += v[cc].x * v[cc].x + v[cc].y * v[cc].y +
                  v[cc].z * v[cc].z + v[cc].w * v[cc].w;
        }
    }

    const float4* kb = reinterpret_cast<const float4*>(g_kn + ((size_t)b * P + h * CK) * L);
    float dk[CK];
#pragma unroll
    for (int kk = 0; kk < CK; kk++) {
        float s = 0.f;
#pragma unroll
        for (int cc = 0; cc < 4; cc++) {
            float4 kv4 = kb[kk * 1024 + cc * 256 + tid];
            s += acc[cc].x * kv4.x + acc[cc].y * kv4.y +
                 acc[cc].z * kv4.z + acc[cc].w * kv4.w;
        }
        dk[kk] = s;
    }

    ss = warpSum(ss);
#pragma unroll
    for (int kk = 0; kk < CK; kk++) dk[kk] = warpSum(dk[kk]);

    __shared__ float sp[8][CK + 1];
    __shared__ float fin[CK + 1];
    if (lane == 0) {
#pragma unroll
        for (int kk = 0; kk < CK; kk++) sp[w][kk] = dk[kk];
        sp[w][CK] = ss;
    }
    __syncthreads();
    if (tid < CK + 1) {
        float s = 0.f;
#pragma unroll
        for (int ww = 0; ww < 8; ww++) s += sp[ww][tid];
        fin[tid] = s;
    }
    __syncthreads();
    if (tid < CK) {
        float inv = 1.f / fmaxf(sqrtf(fin[CK]), 1e-12f);
        float mx = -1e30f;
#pragma unroll
        for (int k2 = 0; k2 < CK; k2++) mx = fmaxf(mx, fin[k2] * inv);
        float sum = 0.f;
#pragma unroll
        for (int k2 = 0; k2 < CK; k2++) sum += expf(fin[k2] * inv - mx);
        g_attn[(size_t)row * CK + tid] = expf(fin[tid] * inv - mx) / sum;
    }
}

// ---------------------------------------------------------------------------
// K4: M[b,o,h*12+kk] = sum_c W[o, h*48+c] * attn[b,h,c,kk]
// ---------------------------------------------------------------------------
__global__ void __launch_bounds__(384) k_fold_w(const float* __restrict__ W) {
    int bh = blockIdx.x;
    int b = bh >> 3, h = bh & 7;
    int o = threadIdx.x;

    __shared__ float sA[CQ * CK];       // attn[c][kk], 576 floats
    const float* ap = g_attn + ((size_t)b * CTOT + h * CQ) * CK;
    for (int i = o; i < CQ * CK; i += 384) sA[i] = ap[i];
    __syncthreads();

    float wreg[CQ];
    const float* wp = W + (size_t)o * CTOT + h * CQ;
#pragma unroll
    for (int cc = 0; cc < CQ; cc++) wreg[cc] = wp[cc];

    float* mp = g_M + ((size_t)b * CTOT + o) * P + h * CK;
#pragma unroll
    for (int kk = 0; kk < CK; kk++) {
        float s = 0.f;
#pragma unroll
        for (int cc = 0; cc < CQ; cc++) s += wreg[cc] * sA[cc * CK + kk];
        mp[kk] = s;
    }
}

// ---------------------------------------------------------------------------
// K5a: f[b,o,j] = sum_p M[b,o,p] * kn[b,p,j] with packed f32x2 FMA.
// Tile: 8 o-rows x 512 j. Grid (jt=8, ot=48, b=2) = 768 blocks x 128 thr.
// O_T=8 cuts regs to ~70 -> ~5 blocks/SM resident, single wave (fixes the
// occ=14% latency exposure seen at O_T=16).
// ---------------------------------------------------------------------------
__global__ void __launch_bounds__(128) k_f() {
    __shared__ float4 sM4[8 * 24];      // [oi][pg] : 4 consecutive p per float4
    int jt = blockIdx.x, ot = blockIdx.y, b = blockIdx.z;
    int tid = threadIdx.x;

    const float4* Mb = reinterpret_cast<const float4*>(g_M + ((size_t)b * CTOT + ot * 8) * P);
    for (int i = tid; i < 8 * 24; i += 128) sM4[i] = Mb[i];
    __syncthreads();

    int j = jt * 512 + tid * 4;
    const float* knb = g_kn + (size_t)b * P * L + j;

    ull accLo[8], accHi[8];
#pragma unroll
    for (int oi = 0; oi < 8; oi++) { accLo[oi] = 0ULL; accHi[oi] = 0ULL; }

#pragma unroll 3
    for (int pg = 0; pg < 24; pg++) {
        ulonglong2 kq[4];
#pragma unroll
        for (int r = 0; r < 4; r++)
            kq[r] = *reinterpret_cast<const ulonglong2*>(knb + (size_t)(pg * 4 + r) * L);
#pragma unroll
        for (int oi = 0; oi < 8; oi++) {
            float4 m = sM4[oi * 24 + pg];
            ull m0 = pack2(m.x), m1 = pack2(m.y), m2 = pack2(m.z), m3 = pack2(m.w);
            ffma2(accLo[oi], kq[0].x, m0); ffma2(accHi[oi], kq[0].y, m0);
            ffma2(accLo[oi], kq[1].x, m1); ffma2(accHi[oi], kq[1].y, m1);
            ffma2(accLo[oi], kq[2].x, m2); ffma2(accHi[oi], kq[2].y, m2);
            ffma2(accLo[oi], kq[3].x, m3); ffma2(accHi[oi], kq[3].y, m3);
        }
    }

#pragma unroll
    for (int oi = 0; oi < 8; oi++) {
        ulonglong2 r;
        r.x = accLo[oi];
        r.y = accHi[oi];
        *reinterpret_cast<ulonglong2*>(g_f + ((size_t)(b * CTOT + ot * 8 + oi)) * L + j) = r;
    }
}

// ---------------------------------------------------------------------------
// K5b: pure replication. Each thread: 1 float4 read of f (L2) + 16 STG.128.
// ---------------------------------------------------------------------------
__global__ void __launch_bounds__(256) k_replicate(float* __restrict__ out) {
    int idx = blockIdx.x * 256 + threadIdx.x;      // float4 index into f
    float4 v = reinterpret_cast<const float4*>(g_f)[idx];
    int row = idx >> 10;
    int j4  = idx & 1023;
    float4* o = reinterpret_cast<float4*>(out) + (size_t)row * 16384 + j4;
#pragma unroll
    for (int t = 0; t < TREP; t++) o[t * 1024] = v;
}

// ---------------------------------------------------------------------------
extern "C" void kernel_launch(void* const* d_in, const int* in_sizes, int n_in,
                              void* d_out, int out_size) {
    const float* Q  = (const float*)d_in[0];
    const float* kv = (const float*)d_in[1];
    const float* W  = (const float*)d_in[2];
    float* out = (float*)d_out;

    k_pool_kv<<<KROWS, 1024>>>(kv);
    // Two tiny deterministic dummy launches (outputs overwritten by the real
    // k_fold_w below) so k_fold_attn is the 4th launch -> ncu captures it.
    k_fold_w<<<1, 384>>>(W);
    k_fold_w<<<1, 384>>>(W);
    k_fold_attn<<<NROWS, 256>>>(Q);
    k_fold_w<<<B * HEADS, 384>>>(W);
    dim3 gf(8, 48, 2);
    k_f<<<gf, 128>>>();
    k_replicate<<<(NROWS * 1024) / 256, 256>>>(out);
}

// round 7
// speedup vs baseline: 1.2947x; 1.2947x over previous
#include <cuda_runtime.h>
#include <math.h>

// Problem constants (fixed shapes)
#define B      2
#define HEADS  8
#define CQ     48
#define CK     12
#define CTOT   384      // HEADS*CQ
#define P      96       // pooled channels = HEADS*CK
#define L      4096
#define TREP   16
#define HW     65536    // 256*256 = TREP*L
#define NROWS  (B*CTOT)     // 768 q rows
#define KROWS  (B*P)        // 192 k rows

typedef unsigned long long ull;

// Scratch (static device globals — no allocation)
__device__ float g_kn[KROWS * L];      // pooled + L2-normalized kv   (3.1 MB)
__device__ float g_attn[NROWS * CK];   // softmax(attn)
__device__ float g_M[B * CTOT * P];    // W folded with attn
__device__ float g_f[NROWS * L];       // pre-replication output      (12.6 MB)

__device__ __forceinline__ float warpSum(float v) {
#pragma unroll
    for (int o = 16; o > 0; o >>= 1) v += __shfl_xor_sync(0xffffffffu, v, o);
    return v;
}

#if defined(__CUDA_ARCH__) && (__CUDA_ARCH__ >= 1000)
__device__ __forceinline__ ull pack2(float x) {      // (x, x) as f32x2
    ull r;
    asm("mov.b64 %0, {%1, %1};" : "=l"(r) : "f"(x));
    return r;
}
__device__ __forceinline__ void ffma2(ull& d, ull a, ull b) {  // d += a*b (2x fp32)
    asm("fma.rn.f32x2 %0, %1, %2, %0;" : "+l"(d) : "l"(a), "l"(b));
}
#else
__device__ __forceinline__ ull pack2(float x) {
    union { float f[2]; ull u; } t; t.f[0] = x; t.f[1] = x; return t.u;
}
__device__ __forceinline__ void ffma2(ull& d, ull a, ull b) {
    union { float f[2]; ull u; } da, aa, ba;
    da.u = d; aa.u = a; ba.u = b;
    da.f[0] = fmaf(aa.f[0], ba.f[0], da.f[0]);
    da.f[1] = fmaf(aa.f[1], ba.f[1], da.f[1]);
    d = da.u;
}
#endif

// ---------------------------------------------------------------------------
// K2: avg_pool1d over channel groups of 4 + L2 normalize each pooled row.
// ---------------------------------------------------------------------------
__global__ void __launch_bounds__(1024) k_pool_kv(const float* __restrict__ kv) {
    int row = blockIdx.x;               // b*P + i
    int b = row / P, i = row % P;
    int tid = threadIdx.x;
    const float4* base = reinterpret_cast<const float4*>(kv + ((size_t)b * CTOT + 4 * i) * L);
    float4 v0 = base[tid];
    float4 v1 = base[1024 + tid];
    float4 v2 = base[2048 + tid];
    float4 v3 = base[3072 + tid];
    float4 p;
    p.x = 0.25f * (v0.x + v1.x + v2.x + v3.x);
    p.y = 0.25f * (v0.y + v1.y + v2.y + v3.y);
    p.z = 0.25f * (v0.z + v1.z + v2.z + v3.z);
    p.w = 0.25f * (v0.w + v1.w + v2.w + v3.w);
    float ss = p.x * p.x + p.y * p.y + p.z * p.z + p.w * p.w;

    ss = warpSum(ss);
    __shared__ float sred[32];
    __shared__ float s_scale;
    int lane = tid & 31, w = tid >> 5;
    if (lane == 0) sred[w] = ss;
    __syncthreads();
    if (w == 0) {
        float v = sred[lane];
        v = warpSum(v);
        if (lane == 0) s_scale = 1.f / fmaxf(sqrtf(v), 1e-12f);
    }
    __syncthreads();
    float sc = s_scale;
    p.x *= sc; p.y *= sc; p.z *= sc; p.w *= sc;
    reinterpret_cast<float4*>(g_kn + (size_t)row * L)[tid] = p;
}

// ---------------------------------------------------------------------------
// K1: fold Q over 16 tiles + dot vs 12 kn rows + softmax -> attn row.
// One block (256 threads) per q-row; 768 blocks.
// __launch_bounds__(256, 6): cap regs at ~42 so 6 blocks/SM are resident ->
// 888 slots >= 768 blocks -> SINGLE WAVE (fixes the 2-wave ragged tail that
// capped DRAM at 54%).
// ---------------------------------------------------------------------------
__global__ void __launch_bounds__(256, 6) k_fold_attn(const float* __restrict__ Q) {
    int row = blockIdx.x;
    int b = row / CTOT;
    int c = row % CTOT;
    int h = c / CQ;
    int tid = threadIdx.x;
    int lane = tid & 31, w = tid >> 5;

    const float4* qp = reinterpret_cast<const float4*>(Q + (size_t)row * HW);
    float4 acc[4];
#pragma unroll
    for (int cc = 0; cc < 4; cc++) acc[cc] = make_float4(0.f, 0.f, 0.f, 0.f);
    float ss = 0.f;

#pragma unroll
    for (int t = 0; t < TREP; t++) {
        float4 v[4];
#pragma unroll
        for (int cc = 0; cc < 4; cc++) v[cc] = qp[t * 1024 + cc * 256 + tid];
#pragma unroll
        for (int cc = 0; cc < 4; cc++) {
            acc[cc].x += v[cc].x; acc[cc].y += v[cc].y;
            acc[cc].z += v[cc].z; acc[cc].w += v[cc].w;
            ss += v[cc].x * v[cc].x + v[cc].y * v[cc].y +
                  v[cc].z * v[cc].z + v[cc].w * v[cc].w;
        }
    }

    const float4* kb = reinterpret_cast<const float4*>(g_kn + ((size_t)b * P + h * CK) * L);
    float dk[CK];
#pragma unroll
    for (int kk = 0; kk < CK; kk++) {
        float s = 0.f;
#pragma unroll
        for (int cc = 0; cc < 4; cc++) {
            float4 kv4 = kb[kk * 1024 + cc * 256 + tid];
            s += acc[cc].x * kv4.x + acc[cc].y * kv4.y +
                 acc[cc].z * kv4.z + acc[cc].w * kv4.w;
        }
        dk[kk] = s;
    }

    ss = warpSum(ss);
#pragma unroll
    for (int kk = 0; kk < CK; kk++) dk[kk] = warpSum(dk[kk]);

    __shared__ float sp[8][CK + 1];
    __shared__ float fin[CK + 1];
    if (lane == 0) {
#pragma unroll
        for (int kk = 0; kk < CK; kk++) sp[w][kk] = dk[kk];
        sp[w][CK] = ss;
    }
    __syncthreads();
    if (tid < CK + 1) {
        float s = 0.f;
#pragma unroll
        for (int ww = 0; ww < 8; ww++) s += sp[ww][tid];
        fin[tid] = s;
    }
    __syncthreads();
    if (tid < CK) {
        float inv = 1.f / fmaxf(sqrtf(fin[CK]), 1e-12f);
        float mx = -1e30f;
#pragma unroll
        for (int k2 = 0; k2 < CK; k2++) mx = fmaxf(mx, fin[k2] * inv);
        float sum = 0.f;
#pragma unroll
        for (int k2 = 0; k2 < CK; k2++) sum += expf(fin[k2] * inv - mx);
        g_attn[(size_t)row * CK + tid] = expf(fin[tid] * inv - mx) / sum;
    }
}

// ---------------------------------------------------------------------------
// K4: M[b,o,h*12+kk] = sum_c W[o, h*48+c] * attn[b,h,c,kk]
// ---------------------------------------------------------------------------
__global__ void __launch_bounds__(384) k_fold_w(const float* __restrict__ W) {
    int bh = blockIdx.x;
    int b = bh >> 3, h = bh & 7;
    int o = threadIdx.x;

    __shared__ float sA[CQ * CK];       // attn[c][kk], 576 floats
    const float* ap = g_attn + ((size_t)b * CTOT + h * CQ) * CK;
    for (int i = o; i < CQ * CK; i += 384) sA[i] = ap[i];
    __syncthreads();

    float wreg[CQ];
    const float* wp = W + (size_t)o * CTOT + h * CQ;
#pragma unroll
    for (int cc = 0; cc < CQ; cc++) wreg[cc] = wp[cc];

    float* mp = g_M + ((size_t)b * CTOT + o) * P + h * CK;
#pragma unroll
    for (int kk = 0; kk < CK; kk++) {
        float s = 0.f;
#pragma unroll
        for (int cc = 0; cc < CQ; cc++) s += wreg[cc] * sA[cc * CK + kk];
        mp[kk] = s;
    }
}

// ---------------------------------------------------------------------------
// K5a: f[b,o,j] = sum_p M[b,o,p] * kn[b,p,j] with packed f32x2 FMA.
// Tile: 8 o-rows x 512 j. Grid (jt=8, ot=48, b=2) = 768 blocks x 128 thr.
// ---------------------------------------------------------------------------
__global__ void __launch_bounds__(128) k_f() {
    __shared__ float4 sM4[8 * 24];      // [oi][pg] : 4 consecutive p per float4
    int jt = blockIdx.x, ot = blockIdx.y, b = blockIdx.z;
    int tid = threadIdx.x;

    const float4* Mb = reinterpret_cast<const float4*>(g_M + ((size_t)b * CTOT + ot * 8) * P);
    for (int i = tid; i < 8 * 24; i += 128) sM4[i] = Mb[i];
    __syncthreads();

    int j = jt * 512 + tid * 4;
    const float* knb = g_kn + (size_t)b * P * L + j;

    ull accLo[8], accHi[8];
#pragma unroll
    for (int oi = 0; oi < 8; oi++) { accLo[oi] = 0ULL; accHi[oi] = 0ULL; }

#pragma unroll 3
    for (int pg = 0; pg < 24; pg++) {
        ulonglong2 kq[4];
#pragma unroll
        for (int r = 0; r < 4; r++)
            kq[r] = *reinterpret_cast<const ulonglong2*>(knb + (size_t)(pg * 4 + r) * L);
#pragma unroll
        for (int oi = 0; oi < 8; oi++) {
            float4 m = sM4[oi * 24 + pg];
            ull m0 = pack2(m.x), m1 = pack2(m.y), m2 = pack2(m.z), m3 = pack2(m.w);
            ffma2(accLo[oi], kq[0].x, m0); ffma2(accHi[oi], kq[0].y, m0);
            ffma2(accLo[oi], kq[1].x, m1); ffma2(accHi[oi], kq[1].y, m1);
            ffma2(accLo[oi], kq[2].x, m2); ffma2(accHi[oi], kq[2].y, m2);
            ffma2(accLo[oi], kq[3].x, m3); ffma2(accHi[oi], kq[3].y, m3);
        }
    }

#pragma unroll
    for (int oi = 0; oi < 8; oi++) {
        ulonglong2 r;
        r.x = accLo[oi];
        r.y = accHi[oi];
        *reinterpret_cast<ulonglong2*>(g_f + ((size_t)(b * CTOT + ot * 8 + oi)) * L + j) = r;
    }
}

// ---------------------------------------------------------------------------
// K5b: pure replication. Each thread: 1 float4 read of f (L2) + 16 STG.128.
// ---------------------------------------------------------------------------
__global__ void __launch_bounds__(256) k_replicate(float* __restrict__ out) {
    int idx = blockIdx.x * 256 + threadIdx.x;      // float4 index into f
    float4 v = reinterpret_cast<const float4*>(g_f)[idx];
    int row = idx >> 10;
    int j4  = idx & 1023;
    float4* o = reinterpret_cast<float4*>(out) + (size_t)row * 16384 + j4;
#pragma unroll
    for (int t = 0; t < TREP; t++) o[t * 1024] = v;
}

// ---------------------------------------------------------------------------
extern "C" void kernel_launch(void* const* d_in, const int* in_sizes, int n_in,
                              void* d_out, int out_size) {
    const float* Q  = (const float*)d_in[0];
    const float* kv = (const float*)d_in[1];
    const float* W  = (const float*)d_in[2];
    float* out = (float*)d_out;

    k_pool_kv<<<KROWS, 1024>>>(kv);
    k_fold_attn<<<NROWS, 256>>>(Q);
    k_fold_w<<<B * HEADS, 384>>>(W);
    dim3 gf(8, 48, 2);
    k_f<<<gf, 128>>>();
    k_replicate<<<(NROWS * 1024) / 256, 256>>>(out);
}

// round 8
// speedup vs baseline: 1.3156x; 1.0161x over previous
#include <cuda_runtime.h>
#include <math.h>

// Problem constants (fixed shapes)
#define B      2
#define HEADS  8
#define CQ     48
#define CK     12
#define CTOT   384      // HEADS*CQ
#define P      96       // pooled channels = HEADS*CK
#define L      4096
#define TREP   16
#define HW     65536    // 256*256 = TREP*L
#define NROWS  (B*CTOT)     // 768 q rows
#define KROWS  (B*P)        // 192 k rows

typedef unsigned long long ull;

// Scratch (static device globals — no allocation)
__device__ float g_kn[KROWS * L];      // pooled + L2-normalized kv   (3.1 MB)
__device__ float g_attn[NROWS * CK];   // softmax(attn)
__device__ float g_M[B * CTOT * P];    // W folded with attn

__device__ __forceinline__ float warpSum(float v) {
#pragma unroll
    for (int o = 16; o > 0; o >>= 1) v += __shfl_xor_sync(0xffffffffu, v, o);
    return v;
}

#if defined(__CUDA_ARCH__) && (__CUDA_ARCH__ >= 1000)
__device__ __forceinline__ ull pack2(float x) {      // (x, x) as f32x2
    ull r;
    asm("mov.b64 %0, {%1, %1};" : "=l"(r) : "f"(x));
    return r;
}
__device__ __forceinline__ void ffma2(ull& d, ull a, ull b) {  // d += a*b (2x fp32)
    asm("fma.rn.f32x2 %0, %1, %2, %0;" : "+l"(d) : "l"(a), "l"(b));
}
#else
__device__ __forceinline__ ull pack2(float x) {
    union { float f[2]; ull u; } t; t.f[0] = x; t.f[1] = x; return t.u;
}
__device__ __forceinline__ void ffma2(ull& d, ull a, ull b) {
    union { float f[2]; ull u; } da, aa, ba;
    da.u = d; aa.u = a; ba.u = b;
    da.f[0] = fmaf(aa.f[0], ba.f[0], da.f[0]);
    da.f[1] = fmaf(aa.f[1], ba.f[1], da.f[1]);
    d = da.u;
}
#endif

// ---------------------------------------------------------------------------
// K2: avg_pool1d over channel groups of 4 + L2 normalize each pooled row.
// ---------------------------------------------------------------------------
__global__ void __launch_bounds__(1024) k_pool_kv(const float* __restrict__ kv) {
    int row = blockIdx.x;               // b*P + i
    int b = row / P, i = row % P;
    int tid = threadIdx.x;
    const float4* base = reinterpret_cast<const float4*>(kv + ((size_t)b * CTOT + 4 * i) * L);
    float4 v0 = base[tid];
    float4 v1 = base[1024 + tid];
    float4 v2 = base[2048 + tid];
    float4 v3 = base[3072 + tid];
    float4 p;
    p.x = 0.25f * (v0.x + v1.x + v2.x + v3.x);
    p.y = 0.25f * (v0.y + v1.y + v2.y + v3.y);
    p.z = 0.25f * (v0.z + v1.z + v2.z + v3.z);
    p.w = 0.25f * (v0.w + v1.w + v2.w + v3.w);
    float ss = p.x * p.x + p.y * p.y + p.z * p.z + p.w * p.w;

    ss = warpSum(ss);
    __shared__ float sred[32];
    __shared__ float s_scale;
    int lane = tid & 31, w = tid >> 5;
    if (lane == 0) sred[w] = ss;
    __syncthreads();
    if (w == 0) {
        float v = sred[lane];
        v = warpSum(v);
        if (lane == 0) s_scale = 1.f / fmaxf(sqrtf(v), 1e-12f);
    }
    __syncthreads();
    float sc = s_scale;
    p.x *= sc; p.y *= sc; p.z *= sc; p.w *= sc;
    reinterpret_cast<float4*>(g_kn + (size_t)row * L)[tid] = p;
}

// ---------------------------------------------------------------------------
// K1: fold Q over 16 tiles + dot vs 12 kn rows + softmax -> attn row.
// One block (256 threads) per q-row; 768 blocks. (256,6): single wave.
// ---------------------------------------------------------------------------
__global__ void __launch_bounds__(256, 6) k_fold_attn(const float* __restrict__ Q) {
    int row = blockIdx.x;
    int b = row / CTOT;
    int c = row % CTOT;
    int h = c / CQ;
    int tid = threadIdx.x;
    int lane = tid & 31, w = tid >> 5;

    const float4* qp = reinterpret_cast<const float4*>(Q + (size_t)row * HW);
    float4 acc[4];
#pragma unroll
    for (int cc = 0; cc < 4; cc++) acc[cc] = make_float4(0.f, 0.f, 0.f, 0.f);
    float ss = 0.f;

#pragma unroll
    for (int t = 0; t < TREP; t++) {
        float4 v[4];
#pragma unroll
        for (int cc = 0; cc < 4; cc++) v[cc] = qp[t * 1024 + cc * 256 + tid];
#pragma unroll
        for (int cc = 0; cc < 4; cc++) {
            acc[cc].x += v[cc].x; acc[cc].y += v[cc].y;
            acc[cc].z += v[cc].z; acc[cc].w += v[cc].w;
            ss += v[cc].x * v[cc].x + v[cc].y * v[cc].y +
                  v[cc].z * v[cc].z + v[cc].w * v[cc].w;
        }
    }

    const float4* kb = reinterpret_cast<const float4*>(g_kn + ((size_t)b * P + h * CK) * L);
    float dk[CK];
#pragma unroll
    for (int kk = 0; kk < CK; kk++) {
        float s = 0.f;
#pragma unroll
        for (int cc = 0; cc < 4; cc++) {
            float4 kv4 = kb[kk * 1024 + cc * 256 + tid];
            s += acc[cc].x * kv4.x + acc[cc].y * kv4.y +
                 acc[cc].z * kv4.z + acc[cc].w * kv4.w;
        }
        dk[kk] = s;
    }

    ss = warpSum(ss);
#pragma unroll
    for (int kk = 0; kk < CK; kk++) dk[kk] = warpSum(dk[kk]);

    __shared__ float sp[8][CK + 1];
    __shared__ float fin[CK + 1];
    if (lane == 0) {
#pragma unroll
        for (int kk = 0; kk < CK; kk++) sp[w][kk] = dk[kk];
        sp[w][CK] = ss;
    }
    __syncthreads();
    if (tid < CK + 1) {
        float s = 0.f;
#pragma unroll
        for (int ww = 0; ww < 8; ww++) s += sp[ww][tid];
        fin[tid] = s;
    }
    __syncthreads();
    if (tid < CK) {
        float inv = 1.f / fmaxf(sqrtf(fin[CK]), 1e-12f);
        float mx = -1e30f;
#pragma unroll
        for (int k2 = 0; k2 < CK; k2++) mx = fmaxf(mx, fin[k2] * inv);
        float sum = 0.f;
#pragma unroll
        for (int k2 = 0; k2 < CK; k2++) sum += expf(fin[k2] * inv - mx);
        g_attn[(size_t)row * CK + tid] = expf(fin[tid] * inv - mx) / sum;
    }
}

// ---------------------------------------------------------------------------
// K4: M[b,o,h*12+kk] = sum_c W[o, h*48+c] * attn[b,h,c,kk]
// ---------------------------------------------------------------------------
__global__ void __launch_bounds__(384) k_fold_w(const float* __restrict__ W) {
    int bh = blockIdx.x;
    int b = bh >> 3, h = bh & 7;
    int o = threadIdx.x;

    __shared__ float sA[CQ * CK];       // attn[c][kk], 576 floats
    const float* ap = g_attn + ((size_t)b * CTOT + h * CQ) * CK;
    for (int i = o; i < CQ * CK; i += 384) sA[i] = ap[i];
    __syncthreads();

    float wreg[CQ];
    const float* wp = W + (size_t)o * CTOT + h * CQ;
#pragma unroll
    for (int cc = 0; cc < CQ; cc++) wreg[cc] = wp[cc];

    float* mp = g_M + ((size_t)b * CTOT + o) * P + h * CK;
#pragma unroll
    for (int kk = 0; kk < CK; kk++) {
        float s = 0.f;
#pragma unroll
        for (int cc = 0; cc < CQ; cc++) s += wreg[cc] * sA[cc * CK + kk];
        mp[kk] = s;
    }
}

// ---------------------------------------------------------------------------
// K5 (fused): f = M @ kn computed with FFMA2, written straight to all 16
// output tile replicas (no intermediate buffer, no second kernel).
// M pre-packed in smem as duplicated (m,m) f32x2 pairs -> LDS.128 broadcast
// feeds FFMA2 directly (no mov.b64 packs in the hot loop).
// Tile: 8 o-rows x 512 j. Grid (jt=8, ot=48, b=2) = 768 blocks x 128 thr.
// ---------------------------------------------------------------------------
__global__ void __launch_bounds__(128) k_out_fused(float* __restrict__ out) {
    __shared__ ull sMp[8 * P];          // packed (m,m) pairs, [oi][p], 6KB
    int jt = blockIdx.x, ot = blockIdx.y, b = blockIdx.z;
    int tid = threadIdx.x;

    const float* Mb = g_M + ((size_t)b * CTOT + ot * 8) * P;
    for (int i = tid; i < 8 * P; i += 128) sMp[i] = pack2(Mb[i]);
    __syncthreads();

    int j = jt * 512 + tid * 4;
    const float* knb = g_kn + (size_t)b * P * L + j;

    ull accLo[8], accHi[8];
#pragma unroll
    for (int oi = 0; oi < 8; oi++) { accLo[oi] = 0ULL; accHi[oi] = 0ULL; }

#pragma unroll 3
    for (int pg = 0; pg < 24; pg++) {
        ulonglong2 kq[4];
#pragma unroll
        for (int r = 0; r < 4; r++)
            kq[r] = *reinterpret_cast<const ulonglong2*>(knb + (size_t)(pg * 4 + r) * L);
#pragma unroll
        for (int oi = 0; oi < 8; oi++) {
            ulonglong2 mp0 = *reinterpret_cast<const ulonglong2*>(&sMp[oi * P + pg * 4]);
            ulonglong2 mp1 = *reinterpret_cast<const ulonglong2*>(&sMp[oi * P + pg * 4 + 2]);
            ffma2(accLo[oi], kq[0].x, mp0.x); ffma2(accHi[oi], kq[0].y, mp0.x);
            ffma2(accLo[oi], kq[1].x, mp0.y); ffma2(accHi[oi], kq[1].y, mp0.y);
            ffma2(accLo[oi], kq[2].x, mp1.x); ffma2(accHi[oi], kq[2].y, mp1.x);
            ffma2(accLo[oi], kq[3].x, mp1.y); ffma2(accHi[oi], kq[3].y, mp1.y);
        }
    }

    // Epilogue: write each computed float4 to all 16 tile replicas (streaming).
#pragma unroll
    for (int oi = 0; oi < 8; oi++) {
        union { ull u[2]; float4 f; } cvt;
        cvt.u[0] = accLo[oi];
        cvt.u[1] = accHi[oi];
        float4 v = cvt.f;
        size_t base = ((size_t)(b * CTOT + ot * 8 + oi)) * HW + j;
        float4* op = reinterpret_cast<float4*>(out + base);
#pragma unroll
        for (int t = 0; t < TREP; t++)
            __stcs(op + t * 1024, v);
    }
}

// ---------------------------------------------------------------------------
extern "C" void kernel_launch(void* const* d_in, const int* in_sizes, int n_in,
                              void* d_out, int out_size) {
    const float* Q  = (const float*)d_in[0];
    const float* kv = (const float*)d_in[1];
    const float* W  = (const float*)d_in[2];
    float* out = (float*)d_out;

    k_pool_kv<<<KROWS, 1024>>>(kv);
    k_fold_attn<<<NROWS, 256>>>(Q);
    k_fold_w<<<B * HEADS, 384>>>(W);
    dim3 go(8, 48, 2);
    k_out_fused<<<go, 128>>>(out);
}